// round 2
// baseline (speedup 1.0000x reference)
#include <cuda_runtime.h>

// Problem constants
#define LSEQ   512
#define DDIM   512
#define NBATCH 64
#define M1     32768            // B*L
#define MT     65536            // 2*B*L
#define LL     (512*512)
#define NEG_INF_F (-1e10f)

// ---------------- scratch (device globals; no allocation allowed) ----------
__device__ float g_h  [(size_t)MT * DDIM];   // MLP hidden (r1 then r2)
__device__ float g_rm [(size_t)MT * DDIM];   // r1m then r2m
__device__ float g_o  [(size_t)NBATCH * LL]; // logits
__device__ float g_o1 [(size_t)NBATCH * LL]; // row softmax
__device__ float g_o2t[(size_t)NBATCH * LL]; // col softmax, stored transposed [b][j][i]
__device__ float g_rc [(size_t)MT * DDIM];   // r1_c then r2_c
__device__ float g_t  [(size_t)MT * DDIM];   // compare hidden

// ---------------------------------------------------------------------------
// Flat GEMM over M=65536 rows, N=512, K in {512,1024}.
// Rows < 32768 come from (A0lo, A1lo); rows >= 32768 from (A0hi, A1hi).
// Columns k<512 come from A0*, k>=512 from A1* (concat support). Each source
// is a row-major [32768 x 512] matrix.
// C = epi(A @ W + bias), epi = optional LeakyReLU then optional row-mask.
// ---------------------------------------------------------------------------
template<int LRELU, int MASK>
__global__ __launch_bounds__(256, 2) void gemm_mlp(
    const float* __restrict__ A0lo, const float* __restrict__ A0hi,
    const float* __restrict__ A1lo, const float* __restrict__ A1hi,
    const float* __restrict__ W,    const float* __restrict__ bias,
    const int*   __restrict__ mlo,  const int*   __restrict__ mhi,
    float* __restrict__ C, int K)
{
    __shared__ float As[8][132];
    __shared__ float Bs[8][132];

    const int t  = threadIdx.x;
    const int m0 = blockIdx.y * 128;
    const int n0 = blockIdx.x * 128;
    const bool lo = (m0 < M1);                 // block-uniform (32768 % 128 == 0)
    const float* Ab0 = lo ? A0lo : A0hi;
    const float* Ab1 = lo ? A1lo : A1hi;
    const int mbase = m0 & (M1 - 1);

    const int arow = t >> 1;                   // 0..127
    const int akq  = (t & 1) << 2;             // 0 or 4
    const int bk   = t >> 5;                   // 0..7
    const int bn   = (t & 31) << 2;            // 0..124
    const int tm   = (t >> 4) << 3;            // 0..120
    const int tn   = (t & 15) << 3;            // 0..120

    float acc[8][8];
    #pragma unroll
    for (int i = 0; i < 8; i++)
        #pragma unroll
        for (int j = 0; j < 8; j++) acc[i][j] = 0.f;

    for (int k0 = 0; k0 < K; k0 += 8) {
        const int kk = k0 + akq;
        const float* Ap = (kk < 512)
            ? (Ab0 + (size_t)(mbase + arow) * 512 + kk)
            : (Ab1 + (size_t)(mbase + arow) * 512 + (kk - 512));
        float4 av = *(const float4*)Ap;
        As[akq + 0][arow] = av.x;
        As[akq + 1][arow] = av.y;
        As[akq + 2][arow] = av.z;
        As[akq + 3][arow] = av.w;

        float4 bv = *(const float4*)(W + (size_t)(k0 + bk) * 512 + n0 + bn);
        *(float4*)&Bs[bk][bn] = bv;
        __syncthreads();

        #pragma unroll
        for (int k = 0; k < 8; k++) {
            float4 a0 = *(const float4*)&As[k][tm];
            float4 a1 = *(const float4*)&As[k][tm + 4];
            float4 b0 = *(const float4*)&Bs[k][tn];
            float4 b1 = *(const float4*)&Bs[k][tn + 4];
            float a[8] = {a0.x, a0.y, a0.z, a0.w, a1.x, a1.y, a1.z, a1.w};
            float b[8] = {b0.x, b0.y, b0.z, b0.w, b1.x, b1.y, b1.z, b1.w};
            #pragma unroll
            for (int i = 0; i < 8; i++)
                #pragma unroll
                for (int j = 0; j < 8; j++)
                    acc[i][j] = fmaf(a[i], b[j], acc[i][j]);
        }
        __syncthreads();
    }

    float bb[8];
    #pragma unroll
    for (int j = 0; j < 8; j++) bb[j] = bias[n0 + tn + j];

    #pragma unroll
    for (int i = 0; i < 8; i++) {
        const int grow = m0 + tm + i;
        float mv = 1.f;
        if (MASK) {
            const int* mp = lo ? mlo : mhi;
            mv = mp[grow & (M1 - 1)] ? 1.f : 0.f;
        }
        float cc[8];
        #pragma unroll
        for (int j = 0; j < 8; j++) {
            float c = acc[i][j] + bb[j];
            if (LRELU) c = (c >= 0.f) ? c : 0.01f * c;
            cc[j] = c * mv;
        }
        float* Cp = C + (size_t)grow * 512 + n0 + tn;
        *(float4*)(Cp)     = make_float4(cc[0], cc[1], cc[2], cc[3]);
        *(float4*)(Cp + 4) = make_float4(cc[4], cc[5], cc[6], cc[7]);
    }
}

// ---------------------------------------------------------------------------
// Batched 512x512x512 GEMM.  C[b] = A[b] @ op(B[b])  (op = T if BTRANS).
// OMASK: C = (m1[i] && m2[j]) ? acc : -1e10  (logits epilogue).
// ---------------------------------------------------------------------------
template<int BTRANS, int OMASK>
__global__ __launch_bounds__(256, 2) void bgemm(
    const float* __restrict__ A, const float* __restrict__ Bm,
    float* __restrict__ C,
    const int* __restrict__ m1, const int* __restrict__ m2)
{
    __shared__ float As[8][132];
    __shared__ float Bs[8][132];

    const int t  = threadIdx.x;
    const int b  = blockIdx.z;
    const int m0 = blockIdx.y * 128;
    const int n0 = blockIdx.x * 128;
    const float* Ab = A  + (size_t)b * LL;
    const float* Bb = Bm + (size_t)b * LL;
    float*       Cb = C  + (size_t)b * LL;

    const int arow = t >> 1;
    const int akq  = (t & 1) << 2;
    const int bk   = t >> 5;
    const int bn   = (t & 31) << 2;
    const int tm   = (t >> 4) << 3;
    const int tn   = (t & 15) << 3;

    float acc[8][8];
    #pragma unroll
    for (int i = 0; i < 8; i++)
        #pragma unroll
        for (int j = 0; j < 8; j++) acc[i][j] = 0.f;

    for (int k0 = 0; k0 < 512; k0 += 8) {
        float4 av = *(const float4*)(Ab + (size_t)(m0 + arow) * 512 + k0 + akq);
        As[akq + 0][arow] = av.x;
        As[akq + 1][arow] = av.y;
        As[akq + 2][arow] = av.z;
        As[akq + 3][arow] = av.w;

        if (BTRANS) {
            float4 bv = *(const float4*)(Bb + (size_t)(n0 + arow) * 512 + k0 + akq);
            Bs[akq + 0][arow] = bv.x;
            Bs[akq + 1][arow] = bv.y;
            Bs[akq + 2][arow] = bv.z;
            Bs[akq + 3][arow] = bv.w;
        } else {
            float4 bv = *(const float4*)(Bb + (size_t)(k0 + bk) * 512 + n0 + bn);
            *(float4*)&Bs[bk][bn] = bv;
        }
        __syncthreads();

        #pragma unroll
        for (int k = 0; k < 8; k++) {
            float4 a0 = *(const float4*)&As[k][tm];
            float4 a1 = *(const float4*)&As[k][tm + 4];
            float4 b0 = *(const float4*)&Bs[k][tn];
            float4 b1 = *(const float4*)&Bs[k][tn + 4];
            float a[8] = {a0.x, a0.y, a0.z, a0.w, a1.x, a1.y, a1.z, a1.w};
            float bv[8] = {b0.x, b0.y, b0.z, b0.w, b1.x, b1.y, b1.z, b1.w};
            #pragma unroll
            for (int i = 0; i < 8; i++)
                #pragma unroll
                for (int j = 0; j < 8; j++)
                    acc[i][j] = fmaf(a[i], bv[j], acc[i][j]);
        }
        __syncthreads();
    }

    int mj[8];
    if (OMASK) {
        #pragma unroll
        for (int j = 0; j < 8; j++) mj[j] = m2[b * 512 + n0 + tn + j];
    }

    #pragma unroll
    for (int i = 0; i < 8; i++) {
        const int gi = m0 + tm + i;
        int mi = 1;
        if (OMASK) mi = m1[b * 512 + gi];
        float cc[8];
        #pragma unroll
        for (int j = 0; j < 8; j++) {
            float c = acc[i][j];
            if (OMASK) c = (mi && mj[j]) ? c : NEG_INF_F;
            cc[j] = c;
        }
        float* Cp = Cb + (size_t)gi * 512 + n0 + tn;
        *(float4*)(Cp)     = make_float4(cc[0], cc[1], cc[2], cc[3]);
        *(float4*)(Cp + 4) = make_float4(cc[4], cc[5], cc[6], cc[7]);
    }
}

// ---------------------------------------------------------------------------
// Row softmax (axis=2):  o1[b,i,:] = softmax(o[b,i,:]) * m1[i] * m2[:]
// One block per row, 256 threads x 2 elements.
// ---------------------------------------------------------------------------
__global__ __launch_bounds__(256) void softmax_row(
    const float* __restrict__ o, float* __restrict__ o1,
    const int* __restrict__ m1, const int* __restrict__ m2)
{
    const int r = blockIdx.x;        // 0..32767
    const int b = r >> 9;
    const int t = threadIdx.x;
    const float* row = o + (size_t)r * 512;

    float x0 = row[t];
    float x1 = row[t + 256];

    __shared__ float smx[8];
    __shared__ float ssm[8];

    float mx = fmaxf(x0, x1);
    #pragma unroll
    for (int s = 16; s; s >>= 1) mx = fmaxf(mx, __shfl_xor_sync(0xffffffffu, mx, s));
    if ((t & 31) == 0) smx[t >> 5] = mx;
    __syncthreads();
    float bm = smx[0];
    #pragma unroll
    for (int w = 1; w < 8; w++) bm = fmaxf(bm, smx[w]);

    float e0 = __expf(x0 - bm);
    float e1 = __expf(x1 - bm);
    float s = e0 + e1;
    #pragma unroll
    for (int sh = 16; sh; sh >>= 1) s += __shfl_xor_sync(0xffffffffu, s, sh);
    if ((t & 31) == 0) ssm[t >> 5] = s;
    __syncthreads();
    float tot = 0.f;
    #pragma unroll
    for (int w = 0; w < 8; w++) tot += ssm[w];

    const float inv = 1.f / tot;
    const float mrow = m1[r] ? 1.f : 0.f;
    const float f0 = e0 * inv * mrow * (m2[b * 512 + t]       ? 1.f : 0.f);
    const float f1 = e1 * inv * mrow * (m2[b * 512 + t + 256] ? 1.f : 0.f);
    o1[(size_t)r * 512 + t]       = f0;
    o1[(size_t)r * 512 + t + 256] = f1;
}

// ---------------------------------------------------------------------------
// Column softmax (axis=1), written TRANSPOSED: o2t[b,j,i].
// Block = (128 columns, one batch); thread owns one column, online pass then
// write pass.
// ---------------------------------------------------------------------------
__global__ __launch_bounds__(128) void softmax_col(
    const float* __restrict__ o, float* __restrict__ o2t,
    const int* __restrict__ m1, const int* __restrict__ m2)
{
    const int b = blockIdx.y;
    const int j = blockIdx.x * 128 + threadIdx.x;

    __shared__ float m1s[512];
    for (int i = threadIdx.x; i < 512; i += 128)
        m1s[i] = m1[b * 512 + i] ? 1.f : 0.f;
    __syncthreads();

    const float* ob = o + (size_t)b * LL;
    float mx = -3.4e38f, sum = 0.f;
    for (int i = 0; i < 512; i++) {
        float v = ob[(size_t)i * 512 + j];
        float nm = fmaxf(mx, v);
        sum = sum * __expf(mx - nm) + __expf(v - nm);
        mx = nm;
    }
    const float inv = 1.f / sum;
    const float mjv = m2[b * 512 + j] ? 1.f : 0.f;

    float* orow = o2t + (size_t)b * LL + (size_t)j * 512;
    for (int i = 0; i < 512; i++) {
        float v = ob[(size_t)i * 512 + j];
        orow[i] = __expf(v - mx) * inv * mjv * m1s[i];
    }
}

// ---------------------------------------------------------------------------
extern "C" void kernel_launch(void* const* d_in, const int* in_sizes, int n_in,
                              void* d_out, int out_size)
{
    (void)in_sizes; (void)n_in; (void)out_size;
    const float* r1    = (const float*)d_in[0];
    const float* r2    = (const float*)d_in[1];
    const int*   mask1 = (const int*)  d_in[2];
    const int*   mask2 = (const int*)  d_in[3];
    const float* W1    = (const float*)d_in[4];
    const float* b1    = (const float*)d_in[5];
    const float* W2    = (const float*)d_in[6];
    const float* b2    = (const float*)d_in[7];
    const float* Wc1   = (const float*)d_in[8];
    const float* bc1   = (const float*)d_in[9];
    const float* Wc2   = (const float*)d_in[10];
    const float* bc2   = (const float*)d_in[11];
    float* out = (float*)d_out;

    float *h, *rm, *o, *o1, *o2t, *rc, *tb;
    cudaGetSymbolAddress((void**)&h,   g_h);
    cudaGetSymbolAddress((void**)&rm,  g_rm);
    cudaGetSymbolAddress((void**)&o,   g_o);
    cudaGetSymbolAddress((void**)&o1,  g_o1);
    cudaGetSymbolAddress((void**)&o2t, g_o2t);
    cudaGetSymbolAddress((void**)&rc,  g_rc);
    cudaGetSymbolAddress((void**)&tb,  g_t);

    const size_t HOFF = (size_t)M1 * 512;
    dim3 gm(4, 512);
    dim3 gb(4, 4, 64);

    // H = lrelu(R @ W1 + b1)
    gemm_mlp<1, 0><<<gm, 256>>>(r1, r2, nullptr, nullptr, W1, b1,
                                nullptr, nullptr, h, 512);
    // RM = lrelu(H @ W2 + b2) * mask
    gemm_mlp<1, 1><<<gm, 256>>>(h, h + HOFF, nullptr, nullptr, W2, b2,
                                mask1, mask2, rm, 512);
    // o = r1m @ r2m^T, masked logits
    bgemm<1, 1><<<gb, 256>>>(rm, rm + HOFF, o, mask1, mask2);
    // softmaxes
    softmax_row<<<32768, 256>>>(o, o1, mask1, mask2);
    softmax_col<<<dim3(4, 64), 128>>>(o, o2t, mask1, mask2);
    // r1_c = o1 @ r2m ;  r2_c = o2^T @ r1m
    bgemm<0, 0><<<gb, 256>>>(o1,  rm + HOFF, rc,        nullptr, nullptr);
    bgemm<0, 0><<<gb, 256>>>(o2t, rm,        rc + HOFF, nullptr, nullptr);
    // T = lrelu([RM | RC] @ Wc1 + bc1)
    gemm_mlp<1, 0><<<gm, 256>>>(rm, rm + HOFF, rc, rc + HOFF, Wc1, bc1,
                                nullptr, nullptr, tb, 1024);
    // OUT = lrelu(T @ Wc2 + bc2) * mask
    gemm_mlp<1, 1><<<gm, 256>>>(tb, tb + HOFF, nullptr, nullptr, Wc2, bc2,
                                mask1, mask2, out, 512);
}

// round 3
// speedup vs baseline: 3.0855x; 3.0855x over previous
#include <cuda_runtime.h>

#define M1 32768
#define LL (512*512)
#define NEG_INF_F (-1e10f)

// ---------------- scratch (device globals; no allocation allowed) ----------
__device__ float g_h  [(size_t)65536 * 512];
__device__ float g_rm [(size_t)65536 * 512];
__device__ float g_o  [(size_t)64 * LL];
__device__ float g_o1 [(size_t)64 * LL];
__device__ float g_o2t[(size_t)64 * LL];
__device__ float g_rc [(size_t)65536 * 512];
__device__ float g_t  [(size_t)65536 * 512];

__device__ __forceinline__ unsigned f2tf(float x) {
    unsigned u;
    asm("cvt.rna.tf32.f32 %0, %1;" : "=r"(u) : "f"(x));
    return u;
}

__device__ __forceinline__ void mma_tf32(float* d, const unsigned* a, const unsigned* b) {
    asm volatile(
        "mma.sync.aligned.m16n8k8.row.col.f32.tf32.tf32.f32 "
        "{%0,%1,%2,%3}, {%4,%5,%6,%7}, {%8,%9}, {%0,%1,%2,%3};"
        : "+f"(d[0]), "+f"(d[1]), "+f"(d[2]), "+f"(d[3])
        : "r"(a[0]), "r"(a[1]), "r"(a[2]), "r"(a[3]), "r"(b[0]), "r"(b[1]));
}

// ---------------------------------------------------------------------------
// Flat GEMM, M=65536 rows, N=512, K in {512,1024}.  TF32 tensor cores.
// Rows < 32768 from (A0lo,A1lo); rows >= 32768 from (A0hi,A1hi).
// k<512 from A0*, k>=512 from A1* (concat).  Each source: row-major [32768x512].
// C = epi(A @ W + bias); epi = optional LeakyReLU then optional row mask.
// ---------------------------------------------------------------------------
template<int LRELU, int MASK>
__global__ __launch_bounds__(256) void gemm_mlp(
    const float* __restrict__ A0lo, const float* __restrict__ A0hi,
    const float* __restrict__ A1lo, const float* __restrict__ A1hi,
    const float* __restrict__ W,    const float* __restrict__ bias,
    const int*   __restrict__ mlo,  const int*   __restrict__ mhi,
    float* __restrict__ C, int K)
{
    __shared__ float As[128][36];   // [m][k], pad 36 -> conflict-free frag loads
    __shared__ float Bs[32][136];   // [k][n], pad 136 -> conflict-free frag loads

    const int t  = threadIdx.x;
    const int m0 = blockIdx.y * 128;
    const int n0 = blockIdx.x * 128;
    const bool lo = (m0 < M1);
    const float* Ab0 = lo ? A0lo : A0hi;
    const float* Ab1 = lo ? A1lo : A1hi;
    const int mbase = m0 & (M1 - 1);

    const int warp = t >> 5, lane = t & 31;
    const int wm = (warp & 1) * 64;
    const int wn = (warp >> 1) * 32;
    const int r  = lane >> 2;      // group id
    const int cq = lane & 3;       // thread-in-group

    float acc[4][4][4];
    #pragma unroll
    for (int i = 0; i < 4; i++)
        #pragma unroll
        for (int j = 0; j < 4; j++)
            #pragma unroll
            for (int q = 0; q < 4; q++) acc[i][j][q] = 0.f;

    float4 ar[4], br[4];

    // prime stage 0
    #pragma unroll
    for (int i = 0; i < 4; i++) {
        int f = t + 256 * i; int row = f >> 3; int kk = (f & 7) * 4;
        const float* src = (kk < 512) ? (Ab0 + (size_t)(mbase + row) * 512 + kk)
                                      : (Ab1 + (size_t)(mbase + row) * 512 + kk - 512);
        ar[i] = *(const float4*)src;
    }
    #pragma unroll
    for (int i = 0; i < 4; i++) {
        int f = t + 256 * i; int brow = f >> 5; int bcol = (f & 31) * 4;
        br[i] = *(const float4*)(W + (size_t)brow * 512 + n0 + bcol);
    }

    for (int k0 = 0; k0 < K; k0 += 32) {
        // commit staged regs to smem (tf32-rounded)
        #pragma unroll
        for (int i = 0; i < 4; i++) {
            int f = t + 256 * i; int row = f >> 3; int kq = (f & 7) * 4;
            As[row][kq + 0] = __uint_as_float(f2tf(ar[i].x));
            As[row][kq + 1] = __uint_as_float(f2tf(ar[i].y));
            As[row][kq + 2] = __uint_as_float(f2tf(ar[i].z));
            As[row][kq + 3] = __uint_as_float(f2tf(ar[i].w));
        }
        #pragma unroll
        for (int i = 0; i < 4; i++) {
            int f = t + 256 * i; int brow = f >> 5; int bcol = (f & 31) * 4;
            float4 v = br[i], w;
            w.x = __uint_as_float(f2tf(v.x));
            w.y = __uint_as_float(f2tf(v.y));
            w.z = __uint_as_float(f2tf(v.z));
            w.w = __uint_as_float(f2tf(v.w));
            *(float4*)&Bs[brow][bcol] = w;
        }
        __syncthreads();

        // prefetch next stage
        if (k0 + 32 < K) {
            #pragma unroll
            for (int i = 0; i < 4; i++) {
                int f = t + 256 * i; int row = f >> 3; int kk = k0 + 32 + (f & 7) * 4;
                const float* src = (kk < 512) ? (Ab0 + (size_t)(mbase + row) * 512 + kk)
                                              : (Ab1 + (size_t)(mbase + row) * 512 + kk - 512);
                ar[i] = *(const float4*)src;
            }
            #pragma unroll
            for (int i = 0; i < 4; i++) {
                int f = t + 256 * i; int brow = k0 + 32 + (f >> 5); int bcol = (f & 31) * 4;
                br[i] = *(const float4*)(W + (size_t)brow * 512 + n0 + bcol);
            }
        }

        // compute 4 k8-steps
        #pragma unroll
        for (int ks = 0; ks < 4; ks++) {
            const int kk = ks * 8;
            unsigned a[4][4], b[4][2];
            #pragma unroll
            for (int mt = 0; mt < 4; mt++) {
                int rb = wm + mt * 16 + r;
                a[mt][0] = __float_as_uint(As[rb    ][kk + cq    ]);
                a[mt][1] = __float_as_uint(As[rb + 8][kk + cq    ]);
                a[mt][2] = __float_as_uint(As[rb    ][kk + cq + 4]);
                a[mt][3] = __float_as_uint(As[rb + 8][kk + cq + 4]);
            }
            #pragma unroll
            for (int nt = 0; nt < 4; nt++) {
                int col = wn + nt * 8 + r;
                b[nt][0] = __float_as_uint(Bs[kk + cq    ][col]);
                b[nt][1] = __float_as_uint(Bs[kk + cq + 4][col]);
            }
            #pragma unroll
            for (int mt = 0; mt < 4; mt++)
                #pragma unroll
                for (int nt = 0; nt < 4; nt++)
                    mma_tf32(acc[mt][nt], a[mt], b[nt]);
        }
        __syncthreads();
    }

    // epilogue
    const int* mp = lo ? mlo : mhi;
    #pragma unroll
    for (int mt = 0; mt < 4; mt++) {
        const int gr0 = m0 + wm + mt * 16 + r;
        const int gr1 = gr0 + 8;
        float mv0 = 1.f, mv1 = 1.f;
        if (MASK) {
            mv0 = mp[gr0 & (M1 - 1)] ? 1.f : 0.f;
            mv1 = mp[gr1 & (M1 - 1)] ? 1.f : 0.f;
        }
        #pragma unroll
        for (int nt = 0; nt < 4; nt++) {
            const int gc = n0 + wn + nt * 8 + cq * 2;
            const float bb0 = bias[gc], bb1 = bias[gc + 1];
            float c0 = acc[mt][nt][0] + bb0;
            float c1 = acc[mt][nt][1] + bb1;
            float c2 = acc[mt][nt][2] + bb0;
            float c3 = acc[mt][nt][3] + bb1;
            if (LRELU) {
                c0 = (c0 >= 0.f) ? c0 : 0.01f * c0;
                c1 = (c1 >= 0.f) ? c1 : 0.01f * c1;
                c2 = (c2 >= 0.f) ? c2 : 0.01f * c2;
                c3 = (c3 >= 0.f) ? c3 : 0.01f * c3;
            }
            *(float2*)(C + (size_t)gr0 * 512 + gc) = make_float2(c0 * mv0, c1 * mv0);
            *(float2*)(C + (size_t)gr1 * 512 + gc) = make_float2(c2 * mv1, c3 * mv1);
        }
    }
}

// ---------------------------------------------------------------------------
// Batched 512x512x512 GEMM, TF32.  C[b] = A[b] @ op(B[b]) (op = T if BTRANS).
// OMASK: C = (m1[i] && m2[j]) ? acc : -1e10.
// ---------------------------------------------------------------------------
template<int BTRANS, int OMASK>
__global__ __launch_bounds__(256) void bgemm(
    const float* __restrict__ A, const float* __restrict__ Bm,
    float* __restrict__ C,
    const int* __restrict__ m1, const int* __restrict__ m2)
{
    __shared__ float As[128][36];
    __shared__ float Bs[32][136];

    const int t  = threadIdx.x;
    const int b  = blockIdx.z;
    const int m0 = blockIdx.y * 128;
    const int n0 = blockIdx.x * 128;
    const float* Ab = A  + (size_t)b * LL;
    const float* Bb = Bm + (size_t)b * LL;
    float*       Cb = C  + (size_t)b * LL;

    const int warp = t >> 5, lane = t & 31;
    const int wm = (warp & 1) * 64;
    const int wn = (warp >> 1) * 32;
    const int r  = lane >> 2;
    const int cq = lane & 3;

    float acc[4][4][4];
    #pragma unroll
    for (int i = 0; i < 4; i++)
        #pragma unroll
        for (int j = 0; j < 4; j++)
            #pragma unroll
            for (int q = 0; q < 4; q++) acc[i][j][q] = 0.f;

    float4 ar[4], br[4];

    #pragma unroll
    for (int i = 0; i < 4; i++) {
        int f = t + 256 * i; int row = f >> 3; int kq = (f & 7) * 4;
        ar[i] = *(const float4*)(Ab + (size_t)(m0 + row) * 512 + kq);
    }
    #pragma unroll
    for (int i = 0; i < 4; i++) {
        int f = t + 256 * i;
        if (BTRANS) {
            int nrow = f >> 3; int kq = (f & 7) * 4;
            br[i] = *(const float4*)(Bb + (size_t)(n0 + nrow) * 512 + kq);
        } else {
            int brow = f >> 5; int bcol = (f & 31) * 4;
            br[i] = *(const float4*)(Bb + (size_t)brow * 512 + n0 + bcol);
        }
    }

    for (int k0 = 0; k0 < 512; k0 += 32) {
        #pragma unroll
        for (int i = 0; i < 4; i++) {
            int f = t + 256 * i; int row = f >> 3; int kq = (f & 7) * 4;
            As[row][kq + 0] = __uint_as_float(f2tf(ar[i].x));
            As[row][kq + 1] = __uint_as_float(f2tf(ar[i].y));
            As[row][kq + 2] = __uint_as_float(f2tf(ar[i].z));
            As[row][kq + 3] = __uint_as_float(f2tf(ar[i].w));
        }
        #pragma unroll
        for (int i = 0; i < 4; i++) {
            int f = t + 256 * i;
            if (BTRANS) {
                int nrow = f >> 3; int kq = (f & 7) * 4;
                Bs[kq + 0][nrow] = __uint_as_float(f2tf(br[i].x));
                Bs[kq + 1][nrow] = __uint_as_float(f2tf(br[i].y));
                Bs[kq + 2][nrow] = __uint_as_float(f2tf(br[i].z));
                Bs[kq + 3][nrow] = __uint_as_float(f2tf(br[i].w));
            } else {
                int brow = f >> 5; int bcol = (f & 31) * 4;
                float4 v = br[i], w;
                w.x = __uint_as_float(f2tf(v.x));
                w.y = __uint_as_float(f2tf(v.y));
                w.z = __uint_as_float(f2tf(v.z));
                w.w = __uint_as_float(f2tf(v.w));
                *(float4*)&Bs[brow][bcol] = w;
            }
        }
        __syncthreads();

        if (k0 + 32 < 512) {
            #pragma unroll
            for (int i = 0; i < 4; i++) {
                int f = t + 256 * i; int row = f >> 3; int kq = k0 + 32 + (f & 7) * 4;
                ar[i] = *(const float4*)(Ab + (size_t)(m0 + row) * 512 + kq);
            }
            #pragma unroll
            for (int i = 0; i < 4; i++) {
                int f = t + 256 * i;
                if (BTRANS) {
                    int nrow = f >> 3; int kq = k0 + 32 + (f & 7) * 4;
                    br[i] = *(const float4*)(Bb + (size_t)(n0 + nrow) * 512 + kq);
                } else {
                    int brow = k0 + 32 + (f >> 5); int bcol = (f & 31) * 4;
                    br[i] = *(const float4*)(Bb + (size_t)brow * 512 + n0 + bcol);
                }
            }
        }

        #pragma unroll
        for (int ks = 0; ks < 4; ks++) {
            const int kk = ks * 8;
            unsigned a[4][4], bfr[4][2];
            #pragma unroll
            for (int mt = 0; mt < 4; mt++) {
                int rb = wm + mt * 16 + r;
                a[mt][0] = __float_as_uint(As[rb    ][kk + cq    ]);
                a[mt][1] = __float_as_uint(As[rb + 8][kk + cq    ]);
                a[mt][2] = __float_as_uint(As[rb    ][kk + cq + 4]);
                a[mt][3] = __float_as_uint(As[rb + 8][kk + cq + 4]);
            }
            #pragma unroll
            for (int nt = 0; nt < 4; nt++) {
                int col = wn + nt * 8 + r;
                bfr[nt][0] = __float_as_uint(Bs[kk + cq    ][col]);
                bfr[nt][1] = __float_as_uint(Bs[kk + cq + 4][col]);
            }
            #pragma unroll
            for (int mt = 0; mt < 4; mt++)
                #pragma unroll
                for (int nt = 0; nt < 4; nt++)
                    mma_tf32(acc[mt][nt], a[mt], bfr[nt]);
        }
        __syncthreads();
    }

    #pragma unroll
    for (int mt = 0; mt < 4; mt++) {
        const int gr0 = m0 + wm + mt * 16 + r;
        const int gr1 = gr0 + 8;
        int mi0 = 1, mi1 = 1;
        if (OMASK) {
            mi0 = m1[b * 512 + gr0];
            mi1 = m1[b * 512 + gr1];
        }
        #pragma unroll
        for (int nt = 0; nt < 4; nt++) {
            const int gc = n0 + wn + nt * 8 + cq * 2;
            float c0 = acc[mt][nt][0], c1 = acc[mt][nt][1];
            float c2 = acc[mt][nt][2], c3 = acc[mt][nt][3];
            if (OMASK) {
                const int mj0 = m2[b * 512 + gc];
                const int mj1 = m2[b * 512 + gc + 1];
                c0 = (mi0 && mj0) ? c0 : NEG_INF_F;
                c1 = (mi0 && mj1) ? c1 : NEG_INF_F;
                c2 = (mi1 && mj0) ? c2 : NEG_INF_F;
                c3 = (mi1 && mj1) ? c3 : NEG_INF_F;
            }
            *(float2*)(Cb + (size_t)gr0 * 512 + gc) = make_float2(c0, c1);
            *(float2*)(Cb + (size_t)gr1 * 512 + gc) = make_float2(c2, c3);
        }
    }
}

// ---------------------------------------------------------------------------
// Row softmax (axis=2):  o1[b,i,:] = softmax(o[b,i,:]) * m1[i] * m2[:]
// ---------------------------------------------------------------------------
__global__ __launch_bounds__(256) void softmax_row(
    const float* __restrict__ o, float* __restrict__ o1,
    const int* __restrict__ m1, const int* __restrict__ m2)
{
    const int r = blockIdx.x;
    const int b = r >> 9;
    const int t = threadIdx.x;
    const float* row = o + (size_t)r * 512;

    float x0 = row[t];
    float x1 = row[t + 256];

    __shared__ float smx[8];
    __shared__ float ssm[8];

    float mx = fmaxf(x0, x1);
    #pragma unroll
    for (int s = 16; s; s >>= 1) mx = fmaxf(mx, __shfl_xor_sync(0xffffffffu, mx, s));
    if ((t & 31) == 0) smx[t >> 5] = mx;
    __syncthreads();
    float bm = smx[0];
    #pragma unroll
    for (int w = 1; w < 8; w++) bm = fmaxf(bm, smx[w]);

    float e0 = __expf(x0 - bm);
    float e1 = __expf(x1 - bm);
    float s = e0 + e1;
    #pragma unroll
    for (int sh = 16; sh; sh >>= 1) s += __shfl_xor_sync(0xffffffffu, s, sh);
    if ((t & 31) == 0) ssm[t >> 5] = s;
    __syncthreads();
    float tot = 0.f;
    #pragma unroll
    for (int w = 0; w < 8; w++) tot += ssm[w];

    const float inv = 1.f / tot;
    const float mrow = m1[r] ? 1.f : 0.f;
    const float f0 = e0 * inv * mrow * (m2[b * 512 + t]       ? 1.f : 0.f);
    const float f1 = e1 * inv * mrow * (m2[b * 512 + t + 256] ? 1.f : 0.f);
    o1[(size_t)r * 512 + t]       = f0;
    o1[(size_t)r * 512 + t + 256] = f1;
}

// ---------------------------------------------------------------------------
// Column softmax (axis=1), written TRANSPOSED: o2t[b,j,i].
// ---------------------------------------------------------------------------
__global__ __launch_bounds__(128) void softmax_col(
    const float* __restrict__ o, float* __restrict__ o2t,
    const int* __restrict__ m1, const int* __restrict__ m2)
{
    const int b = blockIdx.y;
    const int j = blockIdx.x * 128 + threadIdx.x;

    __shared__ float m1s[512];
    for (int i = threadIdx.x; i < 512; i += 128)
        m1s[i] = m1[b * 512 + i] ? 1.f : 0.f;
    __syncthreads();

    const float* ob = o + (size_t)b * LL;
    float mx = -3.4e38f, sum = 0.f;
    for (int i = 0; i < 512; i++) {
        float v = ob[(size_t)i * 512 + j];
        float nm = fmaxf(mx, v);
        sum = sum * __expf(mx - nm) + __expf(v - nm);
        mx = nm;
    }
    const float inv = 1.f / sum;
    const float mjv = m2[b * 512 + j] ? 1.f : 0.f;

    float* orow = o2t + (size_t)b * LL + (size_t)j * 512;
    for (int i = 0; i < 512; i++) {
        float v = ob[(size_t)i * 512 + j];
        orow[i] = __expf(v - mx) * inv * mjv * m1s[i];
    }
}

// ---------------------------------------------------------------------------
extern "C" void kernel_launch(void* const* d_in, const int* in_sizes, int n_in,
                              void* d_out, int out_size)
{
    (void)in_sizes; (void)n_in; (void)out_size;
    const float* r1    = (const float*)d_in[0];
    const float* r2    = (const float*)d_in[1];
    const int*   mask1 = (const int*)  d_in[2];
    const int*   mask2 = (const int*)  d_in[3];
    const float* W1    = (const float*)d_in[4];
    const float* b1    = (const float*)d_in[5];
    const float* W2    = (const float*)d_in[6];
    const float* b2    = (const float*)d_in[7];
    const float* Wc1   = (const float*)d_in[8];
    const float* bc1   = (const float*)d_in[9];
    const float* Wc2   = (const float*)d_in[10];
    const float* bc2   = (const float*)d_in[11];
    float* out = (float*)d_out;

    float *h, *rm, *o, *o1, *o2t, *rc, *tb;
    cudaGetSymbolAddress((void**)&h,   g_h);
    cudaGetSymbolAddress((void**)&rm,  g_rm);
    cudaGetSymbolAddress((void**)&o,   g_o);
    cudaGetSymbolAddress((void**)&o1,  g_o1);
    cudaGetSymbolAddress((void**)&o2t, g_o2t);
    cudaGetSymbolAddress((void**)&rc,  g_rc);
    cudaGetSymbolAddress((void**)&tb,  g_t);

    const size_t HOFF = (size_t)M1 * 512;
    dim3 gm(4, 512);
    dim3 gb(4, 4, 64);

    // H = lrelu(R @ W1 + b1)
    gemm_mlp<1, 0><<<gm, 256>>>(r1, r2, nullptr, nullptr, W1, b1,
                                nullptr, nullptr, h, 512);
    // RM = lrelu(H @ W2 + b2) * mask
    gemm_mlp<1, 1><<<gm, 256>>>(h, h + HOFF, nullptr, nullptr, W2, b2,
                                mask1, mask2, rm, 512);
    // o = r1m @ r2m^T, masked logits
    bgemm<1, 1><<<gb, 256>>>(rm, rm + HOFF, o, mask1, mask2);
    // softmaxes
    softmax_row<<<32768, 256>>>(o, o1, mask1, mask2);
    softmax_col<<<dim3(4, 64), 128>>>(o, o2t, mask1, mask2);
    // r1_c = o1 @ r2m ;  r2_c = o2^T @ r1m
    bgemm<0, 0><<<gb, 256>>>(o1,  rm + HOFF, rc,        nullptr, nullptr);
    bgemm<0, 0><<<gb, 256>>>(o2t, rm,        rc + HOFF, nullptr, nullptr);
    // T = lrelu([RM | RC] @ Wc1 + bc1)
    gemm_mlp<1, 0><<<gm, 256>>>(rm, rm + HOFF, rc, rc + HOFF, Wc1, bc1,
                                nullptr, nullptr, tb, 1024);
    // OUT = lrelu(T @ Wc2 + bc2) * mask
    gemm_mlp<1, 1><<<gm, 256>>>(tb, tb + HOFF, nullptr, nullptr, Wc2, bc2,
                                mask1, mask2, out, 512);
}

// round 7
// speedup vs baseline: 3.0972x; 1.0038x over previous
#include <cuda_runtime.h>

#define M1 32768
#define LL (512*512)
#define NEG_INF_F (-1e10f)

// ---------------- scratch (device globals; no allocation allowed) ----------
__device__ float g_h  [(size_t)65536 * 512];
__device__ float g_rm [(size_t)65536 * 512];
__device__ float g_o  [(size_t)64 * LL];
__device__ float g_o1 [(size_t)64 * LL];
__device__ float g_o2t[(size_t)64 * LL];
__device__ float g_rc [(size_t)65536 * 512];
__device__ float g_t  [(size_t)65536 * 512];

__device__ __forceinline__ unsigned f2tf(float x) {
    unsigned u;
    asm("cvt.rna.tf32.f32 %0, %1;" : "=r"(u) : "f"(x));
    return u;
}

__device__ __forceinline__ void mma_tf32(float* d, const unsigned* a, const unsigned* b) {
    asm volatile(
        "mma.sync.aligned.m16n8k8.row.col.f32.tf32.tf32.f32 "
        "{%0,%1,%2,%3}, {%4,%5,%6,%7}, {%8,%9}, {%0,%1,%2,%3};"
        : "+f"(d[0]), "+f"(d[1]), "+f"(d[2]), "+f"(d[3])
        : "r"(a[0]), "r"(a[1]), "r"(a[2]), "r"(a[3]), "r"(b[0]), "r"(b[1]));
}

// ---------------------------------------------------------------------------
// Flat GEMM, M=65536 rows, N=512, K in {512,1024}.  TF32 tensor cores.
// Rows < 32768 from (A0lo,A1lo); rows >= 32768 from (A0hi,A1hi).
// k<512 from A0*, k>=512 from A1* (concat).  Each source: row-major [32768x512].
// C = epi(A @ W + bias); epi = optional LeakyReLU then optional row mask.
// ---------------------------------------------------------------------------
template<int LRELU, int MASK>
__global__ __launch_bounds__(256) void gemm_mlp(
    const float* __restrict__ A0lo, const float* __restrict__ A0hi,
    const float* __restrict__ A1lo, const float* __restrict__ A1hi,
    const float* __restrict__ W,    const float* __restrict__ bias,
    const int*   __restrict__ mlo,  const int*   __restrict__ mhi,
    float* __restrict__ C, int K)
{
    __shared__ float As[128][36];   // [m][k], pad 36 -> conflict-free frag loads
    __shared__ float Bs[32][136];   // [k][n], pad 136 -> conflict-free frag loads

    const int t  = threadIdx.x;
    const int m0 = blockIdx.y * 128;
    const int n0 = blockIdx.x * 128;
    const bool lo = (m0 < M1);
    const float* Ab0 = lo ? A0lo : A0hi;
    const float* Ab1 = lo ? A1lo : A1hi;
    const int mbase = m0 & (M1 - 1);

    const int warp = t >> 5, lane = t & 31;
    const int wm = (warp & 1) * 64;
    const int wn = (warp >> 1) * 32;
    const int r  = lane >> 2;      // group id
    const int cq = lane & 3;       // thread-in-group

    float acc[4][4][4];
    #pragma unroll
    for (int i = 0; i < 4; i++)
        #pragma unroll
        for (int j = 0; j < 4; j++)
            #pragma unroll
            for (int q = 0; q < 4; q++) acc[i][j][q] = 0.f;

    float4 ar[4], br[4];

    // prime stage 0
    #pragma unroll
    for (int i = 0; i < 4; i++) {
        int f = t + 256 * i; int row = f >> 3; int kk = (f & 7) * 4;
        const float* src = (kk < 512) ? (Ab0 + (size_t)(mbase + row) * 512 + kk)
                                      : (Ab1 + (size_t)(mbase + row) * 512 + kk - 512);
        ar[i] = *(const float4*)src;
    }
    #pragma unroll
    for (int i = 0; i < 4; i++) {
        int f = t + 256 * i; int brow = f >> 5; int bcol = (f & 31) * 4;
        br[i] = *(const float4*)(W + (size_t)brow * 512 + n0 + bcol);
    }

    for (int k0 = 0; k0 < K; k0 += 32) {
        // commit staged regs to smem (tf32-rounded)
        #pragma unroll
        for (int i = 0; i < 4; i++) {
            int f = t + 256 * i; int row = f >> 3; int kq = (f & 7) * 4;
            As[row][kq + 0] = __uint_as_float(f2tf(ar[i].x));
            As[row][kq + 1] = __uint_as_float(f2tf(ar[i].y));
            As[row][kq + 2] = __uint_as_float(f2tf(ar[i].z));
            As[row][kq + 3] = __uint_as_float(f2tf(ar[i].w));
        }
        #pragma unroll
        for (int i = 0; i < 4; i++) {
            int f = t + 256 * i; int brow = f >> 5; int bcol = (f & 31) * 4;
            float4 v = br[i], w;
            w.x = __uint_as_float(f2tf(v.x));
            w.y = __uint_as_float(f2tf(v.y));
            w.z = __uint_as_float(f2tf(v.z));
            w.w = __uint_as_float(f2tf(v.w));
            *(float4*)&Bs[brow][bcol] = w;
        }
        __syncthreads();

        // prefetch next stage
        if (k0 + 32 < K) {
            #pragma unroll
            for (int i = 0; i < 4; i++) {
                int f = t + 256 * i; int row = f >> 3; int kk = k0 + 32 + (f & 7) * 4;
                const float* src = (kk < 512) ? (Ab0 + (size_t)(mbase + row) * 512 + kk)
                                              : (Ab1 + (size_t)(mbase + row) * 512 + kk - 512);
                ar[i] = *(const float4*)src;
            }
            #pragma unroll
            for (int i = 0; i < 4; i++) {
                int f = t + 256 * i; int brow = k0 + 32 + (f >> 5); int bcol = (f & 31) * 4;
                br[i] = *(const float4*)(W + (size_t)brow * 512 + n0 + bcol);
            }
        }

        // compute 4 k8-steps
        #pragma unroll
        for (int ks = 0; ks < 4; ks++) {
            const int kk = ks * 8;
            unsigned a[4][4], b[4][2];
            #pragma unroll
            for (int mt = 0; mt < 4; mt++) {
                int rb = wm + mt * 16 + r;
                a[mt][0] = __float_as_uint(As[rb    ][kk + cq    ]);
                a[mt][1] = __float_as_uint(As[rb + 8][kk + cq    ]);
                a[mt][2] = __float_as_uint(As[rb    ][kk + cq + 4]);
                a[mt][3] = __float_as_uint(As[rb + 8][kk + cq + 4]);
            }
            #pragma unroll
            for (int nt = 0; nt < 4; nt++) {
                int col = wn + nt * 8 + r;
                b[nt][0] = __float_as_uint(Bs[kk + cq    ][col]);
                b[nt][1] = __float_as_uint(Bs[kk + cq + 4][col]);
            }
            #pragma unroll
            for (int mt = 0; mt < 4; mt++)
                #pragma unroll
                for (int nt = 0; nt < 4; nt++)
                    mma_tf32(acc[mt][nt], a[mt], b[nt]);
        }
        __syncthreads();
    }

    // epilogue
    const int* mp = lo ? mlo : mhi;
    #pragma unroll
    for (int mt = 0; mt < 4; mt++) {
        const int gr0 = m0 + wm + mt * 16 + r;
        const int gr1 = gr0 + 8;
        float mv0 = 1.f, mv1 = 1.f;
        if (MASK) {
            mv0 = mp[gr0 & (M1 - 1)] ? 1.f : 0.f;
            mv1 = mp[gr1 & (M1 - 1)] ? 1.f : 0.f;
        }
        #pragma unroll
        for (int nt = 0; nt < 4; nt++) {
            const int gc = n0 + wn + nt * 8 + cq * 2;
            const float bb0 = bias[gc], bb1 = bias[gc + 1];
            float c0 = acc[mt][nt][0] + bb0;
            float c1 = acc[mt][nt][1] + bb1;
            float c2 = acc[mt][nt][2] + bb0;
            float c3 = acc[mt][nt][3] + bb1;
            if (LRELU) {
                c0 = (c0 >= 0.f) ? c0 : 0.01f * c0;
                c1 = (c1 >= 0.f) ? c1 : 0.01f * c1;
                c2 = (c2 >= 0.f) ? c2 : 0.01f * c2;
                c3 = (c3 >= 0.f) ? c3 : 0.01f * c3;
            }
            *(float2*)(C + (size_t)gr0 * 512 + gc) = make_float2(c0 * mv0, c1 * mv0);
            *(float2*)(C + (size_t)gr1 * 512 + gc) = make_float2(c2 * mv1, c3 * mv1);
        }
    }
}

// ---------------------------------------------------------------------------
// Batched 512x512x512 GEMM, TF32.  C[b] = A[b] @ op(B[b]) (op = T if BTRANS).
// OMASK: C = (m1[i] && m2[j]) ? acc : -1e10.
// ---------------------------------------------------------------------------
template<int BTRANS, int OMASK>
__global__ __launch_bounds__(256) void bgemm(
    const float* __restrict__ A, const float* __restrict__ Bm,
    float* __restrict__ C,
    const int* __restrict__ m1, const int* __restrict__ m2)
{
    __shared__ float As[128][36];
    __shared__ float Bs[32][136];

    const int t  = threadIdx.x;
    const int b  = blockIdx.z;
    const int m0 = blockIdx.y * 128;
    const int n0 = blockIdx.x * 128;
    const float* Ab = A  + (size_t)b * LL;
    const float* Bb = Bm + (size_t)b * LL;
    float*       Cb = C  + (size_t)b * LL;

    const int warp = t >> 5, lane = t & 31;
    const int wm = (warp & 1) * 64;
    const int wn = (warp >> 1) * 32;
    const int r  = lane >> 2;
    const int cq = lane & 3;

    float acc[4][4][4];
    #pragma unroll
    for (int i = 0; i < 4; i++)
        #pragma unroll
        for (int j = 0; j < 4; j++)
            #pragma unroll
            for (int q = 0; q < 4; q++) acc[i][j][q] = 0.f;

    float4 ar[4], br[4];

    #pragma unroll
    for (int i = 0; i < 4; i++) {
        int f = t + 256 * i; int row = f >> 3; int kq = (f & 7) * 4;
        ar[i] = *(const float4*)(Ab + (size_t)(m0 + row) * 512 + kq);
    }
    #pragma unroll
    for (int i = 0; i < 4; i++) {
        int f = t + 256 * i;
        if (BTRANS) {
            int nrow = f >> 3; int kq = (f & 7) * 4;
            br[i] = *(const float4*)(Bb + (size_t)(n0 + nrow) * 512 + kq);
        } else {
            int brow = f >> 5; int bcol = (f & 31) * 4;
            br[i] = *(const float4*)(Bb + (size_t)brow * 512 + n0 + bcol);
        }
    }

    for (int k0 = 0; k0 < 512; k0 += 32) {
        #pragma unroll
        for (int i = 0; i < 4; i++) {
            int f = t + 256 * i; int row = f >> 3; int kq = (f & 7) * 4;
            As[row][kq + 0] = __uint_as_float(f2tf(ar[i].x));
            As[row][kq + 1] = __uint_as_float(f2tf(ar[i].y));
            As[row][kq + 2] = __uint_as_float(f2tf(ar[i].z));
            As[row][kq + 3] = __uint_as_float(f2tf(ar[i].w));
        }
        #pragma unroll
        for (int i = 0; i < 4; i++) {
            int f = t + 256 * i;
            if (BTRANS) {
                int nrow = f >> 3; int kq = (f & 7) * 4;
                Bs[kq + 0][nrow] = __uint_as_float(f2tf(br[i].x));
                Bs[kq + 1][nrow] = __uint_as_float(f2tf(br[i].y));
                Bs[kq + 2][nrow] = __uint_as_float(f2tf(br[i].z));
                Bs[kq + 3][nrow] = __uint_as_float(f2tf(br[i].w));
            } else {
                int brow = f >> 5; int bcol = (f & 31) * 4;
                float4 v = br[i], w;
                w.x = __uint_as_float(f2tf(v.x));
                w.y = __uint_as_float(f2tf(v.y));
                w.z = __uint_as_float(f2tf(v.z));
                w.w = __uint_as_float(f2tf(v.w));
                *(float4*)&Bs[brow][bcol] = w;
            }
        }
        __syncthreads();

        if (k0 + 32 < 512) {
            #pragma unroll
            for (int i = 0; i < 4; i++) {
                int f = t + 256 * i; int row = f >> 3; int kq = k0 + 32 + (f & 7) * 4;
                ar[i] = *(const float4*)(Ab + (size_t)(m0 + row) * 512 + kq);
            }
            #pragma unroll
            for (int i = 0; i < 4; i++) {
                int f = t + 256 * i;
                if (BTRANS) {
                    int nrow = f >> 3; int kq = k0 + 32 + (f & 7) * 4;
                    br[i] = *(const float4*)(Bb + (size_t)(n0 + nrow) * 512 + kq);
                } else {
                    int brow = k0 + 32 + (f >> 5); int bcol = (f & 31) * 4;
                    br[i] = *(const float4*)(Bb + (size_t)brow * 512 + n0 + bcol);
                }
            }
        }

        #pragma unroll
        for (int ks = 0; ks < 4; ks++) {
            const int kk = ks * 8;
            unsigned a[4][4], bfr[4][2];
            #pragma unroll
            for (int mt = 0; mt < 4; mt++) {
                int rb = wm + mt * 16 + r;
                a[mt][0] = __float_as_uint(As[rb    ][kk + cq    ]);
                a[mt][1] = __float_as_uint(As[rb + 8][kk + cq    ]);
                a[mt][2] = __float_as_uint(As[rb    ][kk + cq + 4]);
                a[mt][3] = __float_as_uint(As[rb + 8][kk + cq + 4]);
            }
            #pragma unroll
            for (int nt = 0; nt < 4; nt++) {
                int col = wn + nt * 8 + r;
                bfr[nt][0] = __float_as_uint(Bs[kk + cq    ][col]);
                bfr[nt][1] = __float_as_uint(Bs[kk + cq + 4][col]);
            }
            #pragma unroll
            for (int mt = 0; mt < 4; mt++)
                #pragma unroll
                for (int nt = 0; nt < 4; nt++)
                    mma_tf32(acc[mt][nt], a[mt], bfr[nt]);
        }
        __syncthreads();
    }

    #pragma unroll
    for (int mt = 0; mt < 4; mt++) {
        const int gr0 = m0 + wm + mt * 16 + r;
        const int gr1 = gr0 + 8;
        int mi0 = 1, mi1 = 1;
        if (OMASK) {
            mi0 = m1[b * 512 + gr0];
            mi1 = m1[b * 512 + gr1];
        }
        #pragma unroll
        for (int nt = 0; nt < 4; nt++) {
            const int gc = n0 + wn + nt * 8 + cq * 2;
            float c0 = acc[mt][nt][0], c1 = acc[mt][nt][1];
            float c2 = acc[mt][nt][2], c3 = acc[mt][nt][3];
            if (OMASK) {
                const int mj0 = m2[b * 512 + gc];
                const int mj1 = m2[b * 512 + gc + 1];
                c0 = (mi0 && mj0) ? c0 : NEG_INF_F;
                c1 = (mi0 && mj1) ? c1 : NEG_INF_F;
                c2 = (mi1 && mj0) ? c2 : NEG_INF_F;
                c3 = (mi1 && mj1) ? c3 : NEG_INF_F;
            }
            *(float2*)(Cb + (size_t)gr0 * 512 + gc) = make_float2(c0, c1);
            *(float2*)(Cb + (size_t)gr1 * 512 + gc) = make_float2(c2, c3);
        }
    }
}

// ---------------------------------------------------------------------------
// Row softmax (axis=2):  o1[b,i,:] = softmax(o[b,i,:]) * m1[i] * m2[:]
// ---------------------------------------------------------------------------
__global__ __launch_bounds__(256) void softmax_row(
    const float* __restrict__ o, float* __restrict__ o1,
    const int* __restrict__ m1, const int* __restrict__ m2)
{
    const int r = blockIdx.x;
    const int b = r >> 9;
    const int t = threadIdx.x;
    const float* row = o + (size_t)r * 512;

    float x0 = row[t];
    float x1 = row[t + 256];

    __shared__ float smx[8];
    __shared__ float ssm[8];

    float mx = fmaxf(x0, x1);
    #pragma unroll
    for (int s = 16; s; s >>= 1) mx = fmaxf(mx, __shfl_xor_sync(0xffffffffu, mx, s));
    if ((t & 31) == 0) smx[t >> 5] = mx;
    __syncthreads();
    float bm = smx[0];
    #pragma unroll
    for (int w = 1; w < 8; w++) bm = fmaxf(bm, smx[w]);

    float e0 = __expf(x0 - bm);
    float e1 = __expf(x1 - bm);
    float s = e0 + e1;
    #pragma unroll
    for (int sh = 16; sh; sh >>= 1) s += __shfl_xor_sync(0xffffffffu, s, sh);
    if ((t & 31) == 0) ssm[t >> 5] = s;
    __syncthreads();
    float tot = 0.f;
    #pragma unroll
    for (int w = 0; w < 8; w++) tot += ssm[w];

    const float inv = 1.f / tot;
    const float mrow = m1[r] ? 1.f : 0.f;
    const float f0 = e0 * inv * mrow * (m2[b * 512 + t]       ? 1.f : 0.f);
    const float f1 = e1 * inv * mrow * (m2[b * 512 + t + 256] ? 1.f : 0.f);
    o1[(size_t)r * 512 + t]       = f0;
    o1[(size_t)r * 512 + t + 256] = f1;
}

// ---------------------------------------------------------------------------
// Column softmax (axis=1), written TRANSPOSED: o2t[b,j,i].
// ---------------------------------------------------------------------------
__global__ __launch_bounds__(128) void softmax_col(
    const float* __restrict__ o, float* __restrict__ o2t,
    const int* __restrict__ m1, const int* __restrict__ m2)
{
    const int b = blockIdx.y;
    const int j = blockIdx.x * 128 + threadIdx.x;

    __shared__ float m1s[512];
    for (int i = threadIdx.x; i < 512; i += 128)
        m1s[i] = m1[b * 512 + i] ? 1.f : 0.f;
    __syncthreads();

    const float* ob = o + (size_t)b * LL;
    float mx = -3.4e38f, sum = 0.f;
    for (int i = 0; i < 512; i++) {
        float v = ob[(size_t)i * 512 + j];
        float nm = fmaxf(mx, v);
        sum = sum * __expf(mx - nm) + __expf(v - nm);
        mx = nm;
    }
    const float inv = 1.f / sum;
    const float mjv = m2[b * 512 + j] ? 1.f : 0.f;

    float* orow = o2t + (size_t)b * LL + (size_t)j * 512;
    for (int i = 0; i < 512; i++) {
        float v = ob[(size_t)i * 512 + j];
        orow[i] = __expf(v - mx) * inv * mjv * m1s[i];
    }
}

// ---------------------------------------------------------------------------
extern "C" void kernel_launch(void* const* d_in, const int* in_sizes, int n_in,
                              void* d_out, int out_size)
{
    (void)in_sizes; (void)n_in; (void)out_size;
    const float* r1    = (const float*)d_in[0];
    const float* r2    = (const float*)d_in[1];
    const int*   mask1 = (const int*)  d_in[2];
    const int*   mask2 = (const int*)  d_in[3];
    const float* W1    = (const float*)d_in[4];
    const float* b1    = (const float*)d_in[5];
    const float* W2    = (const float*)d_in[6];
    const float* b2    = (const float*)d_in[7];
    const float* Wc1   = (const float*)d_in[8];
    const float* bc1   = (const float*)d_in[9];
    const float* Wc2   = (const float*)d_in[10];
    const float* bc2   = (const float*)d_in[11];
    float* out = (float*)d_out;

    float *h, *rm, *o, *o1, *o2t, *rc, *tb;
    cudaGetSymbolAddress((void**)&h,   g_h);
    cudaGetSymbolAddress((void**)&rm,  g_rm);
    cudaGetSymbolAddress((void**)&o,   g_o);
    cudaGetSymbolAddress((void**)&o1,  g_o1);
    cudaGetSymbolAddress((void**)&o2t, g_o2t);
    cudaGetSymbolAddress((void**)&rc,  g_rc);
    cudaGetSymbolAddress((void**)&tb,  g_t);

    const size_t HOFF = (size_t)M1 * 512;
    dim3 gm(4, 512);
    dim3 gb(4, 4, 64);

    // H = lrelu(R @ W1 + b1)
    gemm_mlp<1, 0><<<gm, 256>>>(r1, r2, nullptr, nullptr, W1, b1,
                                nullptr, nullptr, h, 512);
    // RM = lrelu(H @ W2 + b2) * mask
    gemm_mlp<1, 1><<<gm, 256>>>(h, h + HOFF, nullptr, nullptr, W2, b2,
                                mask1, mask2, rm, 512);
    // o = r1m @ r2m^T, masked logits
    bgemm<1, 1><<<gb, 256>>>(rm, rm + HOFF, o, mask1, mask2);
    // softmaxes
    softmax_row<<<32768, 256>>>(o, o1, mask1, mask2);
    softmax_col<<<dim3(4, 64), 128>>>(o, o2t, mask1, mask2);
    // r1_c = o1 @ r2m ;  r2_c = o2^T @ r1m
    bgemm<0, 0><<<gb, 256>>>(o1,  rm + HOFF, rc,        nullptr, nullptr);
    bgemm<0, 0><<<gb, 256>>>(o2t, rm,        rc + HOFF, nullptr, nullptr);
    // T = lrelu([RM | RC] @ Wc1 + bc1)
    gemm_mlp<1, 0><<<gm, 256>>>(rm, rm + HOFF, rc, rc + HOFF, Wc1, bc1,
                                nullptr, nullptr, tb, 1024);
    // OUT = lrelu(T @ Wc2 + bc2) * mask
    gemm_mlp<1, 1><<<gm, 256>>>(tb, tb + HOFF, nullptr, nullptr, Wc2, bc2,
                                mask1, mask2, out, 512);
}